// round 1
// baseline (speedup 1.0000x reference)
#include <cuda_runtime.h>
#include <math.h>

// Problem dims
#define B_DIM   4096
#define S_DIM   16
#define O_DIM   8
#define J_DIM   32
#define HID     240
#define OUT_HID 512
#define JB      (J_DIM * B_DIM)      // 131072

// ---------------- scratch (device globals; no allocations allowed) ----------
__device__ float g_gh[3 * HID];                         // h_init @ W_hh^T + b_hh
__device__ float g_xpred[B_DIM * S_DIM];
__device__ float g_inno[B_DIM * O_DIM];
__device__ float g_xin[B_DIM * HID];                    // pre-dropout fc_in output
__device__ float g_gx[(size_t)JB * 3 * HID];            // GRU pre-activations (377 MB)
__device__ float g_hnew[(size_t)JB * HID];              // 126 MB
__device__ float g_o1[(size_t)JB * OUT_HID];            // 268 MB

__device__ __forceinline__ float sigmoidf_(float x) {
    return 1.0f / (1.0f + expf(-x));
}

// ---------------- K0: gh = h_init @ W_hh^T + b_hh, plus reg scalar ----------
__global__ void gh_kernel(const float* __restrict__ W_hh,
                          const float* __restrict__ b_hh,
                          const float* __restrict__ h_init,
                          float* __restrict__ out /* d_out base */) {
    int n = blockIdx.x * blockDim.x + threadIdx.x;
    if (n < 3 * HID) {
        float acc = b_hh[n];
        const float* w = W_hh + n * HID;
#pragma unroll 8
        for (int k = 0; k < HID; k++) acc = fmaf(h_init[k], w[k], acc);
        g_gh[n] = acc;
    }
    if (n == 0) {
        const float p1 = 0.5f, p2 = 0.65f;
        float reg = -(p1 * logf(p1) + (1.0f - p1) * logf(1.0f - p1))
                    - (p2 * logf(p2) + (1.0f - p2) * logf(1.0f - p2));
        out[2 * B_DIM * S_DIM] = reg;   // offset 131072
    }
}

// ---------------- K1: per-b prep: x_pred, innovation, x_in ------------------
// feats = [state_inno(16), inno(8), zeros(16), inno(8)] -> only 24 live cols.
__global__ void prep_kernel(const float* __restrict__ y_t,
                            const float* __restrict__ xprev,
                            const float* __restrict__ F,
                            const float* __restrict__ H,
                            const float* __restrict__ W_fc,
                            const float* __restrict__ b_fc) {
    int b = blockIdx.x;
    int t = threadIdx.x;
    __shared__ float xp[S_DIM], si[S_DIM], inn[O_DIM];

    if (t < S_DIM) {
        float acc = 0.f;
        const float* fr = F + t * S_DIM;
#pragma unroll
        for (int k = 0; k < S_DIM; k++) acc = fmaf(xprev[b * S_DIM + k], fr[k], acc);
        xp[t] = acc;
        si[t] = xprev[b * S_DIM + t] - acc;
        g_xpred[b * S_DIM + t] = acc;
    }
    __syncthreads();
    if (t < O_DIM) {
        float acc = 0.f;
        const float* hr = H + t * S_DIM;
#pragma unroll
        for (int s = 0; s < S_DIM; s++) acc = fmaf(xp[s], hr[s], acc);
        float iv = y_t[b * O_DIM + t] - acc;
        inn[t] = iv;
        g_inno[b * O_DIM + t] = iv;
    }
    __syncthreads();
    if (t < HID) {
        const float* w = W_fc + t * 48;
        float acc = b_fc[t];
#pragma unroll
        for (int s = 0; s < S_DIM; s++) acc = fmaf(si[s], w[s], acc);
#pragma unroll
        for (int o = 0; o < O_DIM; o++) acc = fmaf(inn[o], w[16 + o] + w[40 + o], acc);
        g_xin[b * HID + t] = fmaxf(acc, 0.0f);
    }
}

// ---------------- fused register-tiled NT GEMM (128x128x16, 256 thr) --------
// MODE 1: gx  = (xin * mask1(u1)) @ W_ih^T            [M=JB, N=720, K=240]
// MODE 2: o1  = relu(hnew @ W_out1^T + b1) * mask2(u2)[M=JB, N=512, K=240]
// MODE 3: ens = xpred + (o1 @ W_out2^T + b2) . inno   [M=JB, N=128, K=512]
template <int MODE>
__global__ __launch_bounds__(256, 2)
void gemm_fused(const float* __restrict__ Bt,     // weight [N,K] row-major
                const float* __restrict__ aux1,   // M1:u1  M2:b_out1  M3:b_out2
                const float* __restrict__ aux2,   // M2:u2  else unused
                float* __restrict__ OutParam) {   // M3: ensemble region of d_out
    constexpr int BM = 128, BN = 128, BK = 16;
    constexpr int K = (MODE == 3) ? 512 : 240;
    constexpr int N = (MODE == 1) ? 720 : ((MODE == 2) ? 512 : 128);
    constexpr int NKT = K / BK;

    const float* Ain = (MODE == 1) ? g_xin : ((MODE == 2) ? g_hnew : g_o1);
    float* Out = (MODE == 1) ? g_gx : ((MODE == 2) ? g_o1 : OutParam);

    __shared__ float As[BK][BM + 4];
    __shared__ float Bs[BK][BN + 4];

    const int tid = threadIdx.x;
    const int tx = tid & 15;        // n-tile: 16 * 8 = 128
    const int ty = tid >> 4;        // m-tile: 16 * 8 = 128
    const int m0 = blockIdx.x * BM;
    const int n0 = blockIdx.y * BN;

    int am[2], ak[2];
#pragma unroll
    for (int i = 0; i < 2; i++) {
        int f = tid + i * 256;      // float4 slot in [0,512)
        am[i] = f >> 2;             // row / n within tile
        ak[i] = (f & 3) << 2;       // k offset (0,4,8,12)
    }

    float4 ra[2], rb[2];

    auto fetch = [&](int kt) {
#pragma unroll
        for (int i = 0; i < 2; i++) {
            int grow = m0 + am[i];
            int gk = kt * BK + ak[i];
            if (MODE == 1) {
                int b = grow & (B_DIM - 1);
                float4 x = *reinterpret_cast<const float4*>(Ain + b * HID + gk);
                float4 u = *reinterpret_cast<const float4*>(aux1 + grow * HID + gk);
                ra[i].x = (u.x > 0.5f) ? 2.0f * x.x : 0.0f;
                ra[i].y = (u.y > 0.5f) ? 2.0f * x.y : 0.0f;
                ra[i].z = (u.z > 0.5f) ? 2.0f * x.z : 0.0f;
                ra[i].w = (u.w > 0.5f) ? 2.0f * x.w : 0.0f;
            } else {
                ra[i] = *reinterpret_cast<const float4*>(Ain + grow * K + gk);
            }
            int gn = n0 + am[i];
            if ((N % BN == 0) || gn < N)
                rb[i] = *reinterpret_cast<const float4*>(Bt + gn * K + gk);
            else
                rb[i] = make_float4(0.f, 0.f, 0.f, 0.f);
        }
    };
    auto stage = [&]() {
#pragma unroll
        for (int i = 0; i < 2; i++) {
            As[ak[i] + 0][am[i]] = ra[i].x;
            As[ak[i] + 1][am[i]] = ra[i].y;
            As[ak[i] + 2][am[i]] = ra[i].z;
            As[ak[i] + 3][am[i]] = ra[i].w;
            Bs[ak[i] + 0][am[i]] = rb[i].x;
            Bs[ak[i] + 1][am[i]] = rb[i].y;
            Bs[ak[i] + 2][am[i]] = rb[i].z;
            Bs[ak[i] + 3][am[i]] = rb[i].w;
        }
    };

    float acc[8][8];
#pragma unroll
    for (int i = 0; i < 8; i++)
#pragma unroll
        for (int q = 0; q < 8; q++) acc[i][q] = 0.f;

    fetch(0);
    stage();
    __syncthreads();

    for (int kt = 0; kt < NKT; ++kt) {
        if (kt + 1 < NKT) fetch(kt + 1);
#pragma unroll
        for (int k = 0; k < BK; k++) {
            float4 a0 = *reinterpret_cast<const float4*>(&As[k][ty * 8]);
            float4 a1 = *reinterpret_cast<const float4*>(&As[k][ty * 8 + 4]);
            float4 b0 = *reinterpret_cast<const float4*>(&Bs[k][tx * 8]);
            float4 b1 = *reinterpret_cast<const float4*>(&Bs[k][tx * 8 + 4]);
            float a[8] = {a0.x, a0.y, a0.z, a0.w, a1.x, a1.y, a1.z, a1.w};
            float bb[8] = {b0.x, b0.y, b0.z, b0.w, b1.x, b1.y, b1.z, b1.w};
#pragma unroll
            for (int i = 0; i < 8; i++)
#pragma unroll
                for (int q = 0; q < 8; q++)
                    acc[i][q] = fmaf(a[i], bb[q], acc[i][q]);
        }
        __syncthreads();
        if (kt + 1 < NKT) {
            stage();
            __syncthreads();
        }
    }

    // ------------- epilogues -------------
    if (MODE == 1) {
        int gn = n0 + tx * 8;
        if (gn < N) {               // 720 % 8 == 0: all-or-nothing per thread
#pragma unroll
            for (int i = 0; i < 8; i++) {
                int row = m0 + ty * 8 + i;
                float4 v0 = make_float4(acc[i][0], acc[i][1], acc[i][2], acc[i][3]);
                float4 v1 = make_float4(acc[i][4], acc[i][5], acc[i][6], acc[i][7]);
                *reinterpret_cast<float4*>(Out + row * 720 + gn) = v0;
                *reinterpret_cast<float4*>(Out + row * 720 + gn + 4) = v1;
            }
        }
    } else if (MODE == 2) {
        int gn = n0 + tx * 8;
        float4 bi0 = *reinterpret_cast<const float4*>(aux1 + gn);
        float4 bi1 = *reinterpret_cast<const float4*>(aux1 + gn + 4);
        float bi[8] = {bi0.x, bi0.y, bi0.z, bi0.w, bi1.x, bi1.y, bi1.z, bi1.w};
#pragma unroll
        for (int i = 0; i < 8; i++) {
            int row = m0 + ty * 8 + i;
            float4 u0 = *reinterpret_cast<const float4*>(aux2 + row * OUT_HID + gn);
            float4 u1v = *reinterpret_cast<const float4*>(aux2 + row * OUT_HID + gn + 4);
            float uu[8] = {u0.x, u0.y, u0.z, u0.w, u1v.x, u1v.y, u1v.z, u1v.w};
            float v[8];
#pragma unroll
            for (int q = 0; q < 8; q++) {
                float t = fmaxf(acc[i][q] + bi[q], 0.0f);
                v[q] = (uu[q] > 0.65f) ? t * (1.0f / 0.35f) : 0.0f;
            }
            *reinterpret_cast<float4*>(Out + row * OUT_HID + gn) =
                make_float4(v[0], v[1], v[2], v[3]);
            *reinterpret_cast<float4*>(Out + row * OUT_HID + gn + 4) =
                make_float4(v[4], v[5], v[6], v[7]);
        }
    } else {  // MODE 3: thread owns cols tx*8..tx*8+7 == K[s=tx, o=0..7]
        float bo[8];
#pragma unroll
        for (int o = 0; o < 8; o++) bo[o] = aux1[tx * 8 + o];
#pragma unroll
        for (int i = 0; i < 8; i++) {
            int row = m0 + ty * 8 + i;
            int b = row & (B_DIM - 1);
            int j = row >> 12;
            float corr = 0.f;
#pragma unroll
            for (int o = 0; o < 8; o++)
                corr = fmaf(acc[i][o] + bo[o], g_inno[b * O_DIM + o], corr);
            Out[b * (J_DIM * S_DIM) + j * S_DIM + tx] =
                g_xpred[b * S_DIM + tx] + corr;
        }
    }
}

// ---------------- K3: GRU pointwise ----------------------------------------
__global__ void gru_kernel(const float* __restrict__ b_ih,
                           const float* __restrict__ h_init) {
    int idx = blockIdx.x * blockDim.x + threadIdx.x;
    if (idx >= JB * HID) return;
    int row = idx / HID;
    int h = idx - row * HID;
    const float* gx = g_gx + (size_t)row * (3 * HID);
    float r = sigmoidf_(gx[h] + b_ih[h] + g_gh[h]);
    float z = sigmoidf_(gx[HID + h] + b_ih[HID + h] + g_gh[HID + h]);
    float n = tanhf(gx[2 * HID + h] + b_ih[2 * HID + h] + r * g_gh[2 * HID + h]);
    g_hnew[idx] = (1.0f - z) * n + z * h_init[h];
}

// ---------------- K6: mean / unbiased var over J ----------------------------
__global__ void reduce_kernel(const float* __restrict__ ens,
                              float* __restrict__ out) {
    int idx = blockIdx.x * blockDim.x + threadIdx.x;   // b*16+s
    if (idx >= B_DIM * S_DIM) return;
    int b = idx >> 4;
    int s = idx & 15;
    const float* p = ens + b * (J_DIM * S_DIM) + s;
    float v[J_DIM];
    float sum = 0.f;
#pragma unroll
    for (int j = 0; j < J_DIM; j++) {
        v[j] = p[j * S_DIM];
        sum += v[j];
    }
    float mean = sum * (1.0f / J_DIM);
    float var = 0.f;
#pragma unroll
    for (int j = 0; j < J_DIM; j++) {
        float d = v[j] - mean;
        var = fmaf(d, d, var);
    }
    out[idx] = mean;
    out[B_DIM * S_DIM + idx] = var * (1.0f / (J_DIM - 1));
}

// ---------------- launcher --------------------------------------------------
extern "C" void kernel_launch(void* const* d_in, const int* in_sizes, int n_in,
                              void* d_out, int out_size) {
    const float* y_t    = (const float*)d_in[0];
    const float* xprev  = (const float*)d_in[1];
    const float* F      = (const float*)d_in[2];
    const float* H      = (const float*)d_in[3];
    const float* W_fc   = (const float*)d_in[4];
    const float* b_fc   = (const float*)d_in[5];
    const float* W_ih   = (const float*)d_in[6];
    const float* W_hh   = (const float*)d_in[7];
    const float* b_ih   = (const float*)d_in[8];
    const float* b_hh   = (const float*)d_in[9];
    const float* W_out1 = (const float*)d_in[10];
    const float* b_out1 = (const float*)d_in[11];
    const float* W_out2 = (const float*)d_in[12];
    const float* b_out2 = (const float*)d_in[13];
    const float* h_init = (const float*)d_in[14];
    const float* u1     = (const float*)d_in[15];
    const float* u2     = (const float*)d_in[16];

    float* out = (float*)d_out;
    float* ens = out + 2 * B_DIM * S_DIM + 1;   // ensemble region

    gh_kernel<<<3, 256>>>(W_hh, b_hh, h_init, out);
    prep_kernel<<<B_DIM, 256>>>(y_t, xprev, F, H, W_fc, b_fc);

    // G1: gx = (xin*mask1) @ W_ih^T   [131072, 720]
    gemm_fused<1><<<dim3(JB / 128, 6), 256>>>(W_ih, u1, nullptr, nullptr);

    // GRU pointwise -> h_new
    gru_kernel<<<(JB * HID) / 256, 256>>>(b_ih, h_init);

    // G2: o1 = relu(h_new @ W_out1^T + b) * mask2   [131072, 512]
    gemm_fused<2><<<dim3(JB / 128, 4), 256>>>(W_out1, b_out1, u2, nullptr);

    // G3: ensemble = xpred + K @ inno   [131072, 128] -> [B,J,S]
    gemm_fused<3><<<dim3(JB / 128, 1), 256>>>(W_out2, b_out2, nullptr, ens);

    // mean / var over J
    reduce_kernel<<<(B_DIM * S_DIM) / 256, 256>>>(ens, out);
}

// round 3
// speedup vs baseline: 1.8383x; 1.8383x over previous
#include <cuda_runtime.h>
#include <cuda_bf16.h>
#include <cstdint>
#include <math.h>

// ---------------- problem dims ----------------------------------------------
#define B_DIM   4096
#define S_DIM   16
#define O_DIM   8
#define J_DIM   32
#define HID     240
#define OUT_HID 512
#define JB      (J_DIM * B_DIM)      // 131072
#define KPAD    256                  // HID padded to 256

// ---------------- scratch (device globals) ----------------------------------
__device__ float g_gh[3 * HID];
__device__ float g_xpred[B_DIM * S_DIM];
__device__ float g_inno[B_DIM * O_DIM];
__device__ float g_xin[B_DIM * HID];
__device__ float g_gx[(size_t)JB * 720];                 // GRU pre-activations fp32

__device__ __nv_bfloat16 g_A1h[(size_t)JB * KPAD];       // (xin*mask1) split
__device__ __nv_bfloat16 g_A1l[(size_t)JB * KPAD];
__device__ __nv_bfloat16 g_A2h[(size_t)JB * KPAD];       // h_new split
__device__ __nv_bfloat16 g_A2l[(size_t)JB * KPAD];
__device__ __nv_bfloat16 g_O1h[(size_t)JB * OUT_HID];    // o1 split
__device__ __nv_bfloat16 g_O1l[(size_t)JB * OUT_HID];
__device__ __nv_bfloat16 g_Wihh[768 * KPAD], g_Wihl[768 * KPAD];
__device__ __nv_bfloat16 g_Wo1h[512 * KPAD], g_Wo1l[512 * KPAD];
__device__ __nv_bfloat16 g_Wo2h[128 * 512],  g_Wo2l[128 * 512];

// ---------------- small helpers ---------------------------------------------
__device__ __forceinline__ uint32_t smem_u32(const void* p) {
    uint32_t a;
    asm("{ .reg .u64 t; cvta.to.shared.u64 t, %1; cvt.u32.u64 %0, t; }" : "=r"(a) : "l"(p));
    return a;
}
__device__ __forceinline__ void ldsm4(uint32_t* r, uint32_t addr) {
    asm volatile("ldmatrix.sync.aligned.m8n8.x4.shared.b16 {%0,%1,%2,%3}, [%4];"
                 : "=r"(r[0]), "=r"(r[1]), "=r"(r[2]), "=r"(r[3]) : "r"(addr));
}
__device__ __forceinline__ void mma16816(float* c, const uint32_t* a, const uint32_t* b) {
    asm volatile(
        "mma.sync.aligned.m16n8k16.row.col.f32.bf16.bf16.f32 "
        "{%0,%1,%2,%3}, {%4,%5,%6,%7}, {%8,%9}, {%0,%1,%2,%3};"
        : "+f"(c[0]), "+f"(c[1]), "+f"(c[2]), "+f"(c[3])
        : "r"(a[0]), "r"(a[1]), "r"(a[2]), "r"(a[3]), "r"(b[0]), "r"(b[1]));
}
__device__ __forceinline__ void cpasync16(uint32_t dst, const void* src) {
    asm volatile("cp.async.cg.shared.global [%0], [%1], 16;" :: "r"(dst), "l"(src));
}

__device__ __forceinline__ float fsig(float x) {
    float e, r;
    asm("ex2.approx.ftz.f32 %0, %1;" : "=f"(e) : "f"(-x * 1.4426950408889634f));
    asm("rcp.approx.ftz.f32 %0, %1;" : "=f"(r) : "f"(1.0f + e));
    return r;
}
__device__ __forceinline__ float ftanh_(float x) { return 2.0f * fsig(2.0f * x) - 1.0f; }

__device__ __forceinline__ void fsplit(float v, __nv_bfloat16& h, __nv_bfloat16& l) {
    h = __float2bfloat16_rn(v);
    l = __float2bfloat16_rn(v - __bfloat162float(h));
}

// ---------------- K0: gh + reg scalar ---------------------------------------
__global__ void gh_kernel(const float* __restrict__ W_hh, const float* __restrict__ b_hh,
                          const float* __restrict__ h_init, float* __restrict__ out) {
    int n = blockIdx.x * blockDim.x + threadIdx.x;
    if (n < 3 * HID) {
        float acc = b_hh[n];
        const float* w = W_hh + n * HID;
#pragma unroll 8
        for (int k = 0; k < HID; k++) acc = fmaf(h_init[k], w[k], acc);
        g_gh[n] = acc;
    }
    if (n == 0) {
        const float p1 = 0.5f, p2 = 0.65f;
        out[2 * B_DIM * S_DIM] =
            -(p1 * logf(p1) + (1.0f - p1) * logf(1.0f - p1))
            - (p2 * logf(p2) + (1.0f - p2) * logf(1.0f - p2));
    }
}

// ---------------- K1: per-b prep --------------------------------------------
__global__ void prep_kernel(const float* __restrict__ y_t, const float* __restrict__ xprev,
                            const float* __restrict__ F, const float* __restrict__ H,
                            const float* __restrict__ W_fc, const float* __restrict__ b_fc) {
    int b = blockIdx.x;
    int t = threadIdx.x;
    __shared__ float xp[S_DIM], si[S_DIM], inn[O_DIM];
    if (t < S_DIM) {
        float acc = 0.f;
        const float* fr = F + t * S_DIM;
#pragma unroll
        for (int k = 0; k < S_DIM; k++) acc = fmaf(xprev[b * S_DIM + k], fr[k], acc);
        xp[t] = acc;
        si[t] = xprev[b * S_DIM + t] - acc;
        g_xpred[b * S_DIM + t] = acc;
    }
    __syncthreads();
    if (t < O_DIM) {
        float acc = 0.f;
        const float* hr = H + t * S_DIM;
#pragma unroll
        for (int s = 0; s < S_DIM; s++) acc = fmaf(xp[s], hr[s], acc);
        float iv = y_t[b * O_DIM + t] - acc;
        inn[t] = iv;
        g_inno[b * O_DIM + t] = iv;
    }
    __syncthreads();
    if (t < HID) {
        const float* w = W_fc + t * 48;
        float acc = b_fc[t];
#pragma unroll
        for (int s = 0; s < S_DIM; s++) acc = fmaf(si[s], w[s], acc);
#pragma unroll
        for (int o = 0; o < O_DIM; o++) acc = fmaf(inn[o], w[16 + o] + w[40 + o], acc);
        g_xin[b * HID + t] = fmaxf(acc, 0.0f);
    }
}

// ---------------- weight conversion (split bf16, padded) --------------------
__global__ void convW_kernel(const float* __restrict__ W_ih,
                             const float* __restrict__ W_o1,
                             const float* __restrict__ W_o2) {
    int g = blockIdx.x * blockDim.x + threadIdx.x;
    const int N1 = 768 * KPAD, N2 = 512 * KPAD, N3 = 128 * 512;
    if (g < N1) {
        int n = g / KPAD, k = g - n * KPAD;
        float v = (n < 720 && k < 240) ? W_ih[n * 240 + k] : 0.f;
        fsplit(v, g_Wihh[g], g_Wihl[g]);
    } else if (g < N1 + N2) {
        int i = g - N1;
        int n = i / KPAD, k = i - n * KPAD;
        float v = (k < 240) ? W_o1[n * 240 + k] : 0.f;
        fsplit(v, g_Wo1h[i], g_Wo1l[i]);
    } else if (g < N1 + N2 + N3) {
        int i = g - N1 - N2;
        fsplit(W_o2[i], g_Wo2h[i], g_Wo2l[i]);
    }
}

// ---------------- conv1: A1 = split(xin * mask1) ----------------------------
__global__ void conv1_kernel(const float* __restrict__ u1) {
    int g = blockIdx.x * blockDim.x + threadIdx.x;   // row*64 + k4
    if (g >= JB * 64) return;
    int row = g >> 6, k4 = g & 63;
    __nv_bfloat16 hh[4], ll[4];
    if (k4 < 60) {
        int b = row & (B_DIM - 1);
        float4 x = *reinterpret_cast<const float4*>(g_xin + b * HID + 4 * k4);
        float4 u = *reinterpret_cast<const float4*>(u1 + (size_t)row * HID + 4 * k4);
        float v0 = (u.x > 0.5f) ? 2.0f * x.x : 0.f;
        float v1 = (u.y > 0.5f) ? 2.0f * x.y : 0.f;
        float v2 = (u.z > 0.5f) ? 2.0f * x.z : 0.f;
        float v3 = (u.w > 0.5f) ? 2.0f * x.w : 0.f;
        fsplit(v0, hh[0], ll[0]); fsplit(v1, hh[1], ll[1]);
        fsplit(v2, hh[2], ll[2]); fsplit(v3, hh[3], ll[3]);
    } else {
#pragma unroll
        for (int e = 0; e < 4; e++) { hh[e] = __float2bfloat16_rn(0.f); ll[e] = hh[e]; }
    }
    *reinterpret_cast<uint2*>(g_A1h + (size_t)row * KPAD + 4 * k4) = *reinterpret_cast<uint2*>(hh);
    *reinterpret_cast<uint2*>(g_A1l + (size_t)row * KPAD + 4 * k4) = *reinterpret_cast<uint2*>(ll);
}

// ---------------- conv2: GRU pointwise -> A2 split --------------------------
__global__ void conv2_kernel(const float* __restrict__ b_ih, const float* __restrict__ h_init) {
    int g = blockIdx.x * blockDim.x + threadIdx.x;
    if (g >= JB * 64) return;
    int row = g >> 6, k4 = g & 63;
    __nv_bfloat16 hh[4], ll[4];
    if (k4 < 60) {
        const float* gx = g_gx + (size_t)row * 720 + 4 * k4;
        float4 xr = *reinterpret_cast<const float4*>(gx);
        float4 xz = *reinterpret_cast<const float4*>(gx + 240);
        float4 xn = *reinterpret_cast<const float4*>(gx + 480);
        float4 br = *reinterpret_cast<const float4*>(b_ih + 4 * k4);
        float4 bz = *reinterpret_cast<const float4*>(b_ih + 240 + 4 * k4);
        float4 bn = *reinterpret_cast<const float4*>(b_ih + 480 + 4 * k4);
        float4 gr = *reinterpret_cast<const float4*>(g_gh + 4 * k4);
        float4 gz = *reinterpret_cast<const float4*>(g_gh + 240 + 4 * k4);
        float4 gn = *reinterpret_cast<const float4*>(g_gh + 480 + 4 * k4);
        float4 hi = *reinterpret_cast<const float4*>(h_init + 4 * k4);
        float vr[4] = {xr.x, xr.y, xr.z, xr.w}, vz[4] = {xz.x, xz.y, xz.z, xz.w};
        float vn[4] = {xn.x, xn.y, xn.z, xn.w};
        float cbr[4] = {br.x, br.y, br.z, br.w}, cbz[4] = {bz.x, bz.y, bz.z, bz.w};
        float cbn[4] = {bn.x, bn.y, bn.z, bn.w};
        float cgr[4] = {gr.x, gr.y, gr.z, gr.w}, cgz[4] = {gz.x, gz.y, gz.z, gz.w};
        float cgn[4] = {gn.x, gn.y, gn.z, gn.w};
        float chi[4] = {hi.x, hi.y, hi.z, hi.w};
#pragma unroll
        for (int e = 0; e < 4; e++) {
            float r = fsig(vr[e] + cbr[e] + cgr[e]);
            float z = fsig(vz[e] + cbz[e] + cgz[e]);
            float n = ftanh_(vn[e] + cbn[e] + r * cgn[e]);
            float h = (1.0f - z) * n + z * chi[e];
            fsplit(h, hh[e], ll[e]);
        }
    } else {
#pragma unroll
        for (int e = 0; e < 4; e++) { hh[e] = __float2bfloat16_rn(0.f); ll[e] = hh[e]; }
    }
    *reinterpret_cast<uint2*>(g_A2h + (size_t)row * KPAD + 4 * k4) = *reinterpret_cast<uint2*>(hh);
    *reinterpret_cast<uint2*>(g_A2l + (size_t)row * KPAD + 4 * k4) = *reinterpret_cast<uint2*>(ll);
}

// ---------------- mma.sync split-bf16 GEMM ----------------------------------
// 128x128 block, BK=32, 8 warps (2m x 4n), warp tile 64x32, m16n8k16.
// SMEM: per stage 4 arrays (Ah, Al, Bh, Bl), 128 rows x 32 bf16, row stride 80B.
// MODE 1: gx  = A1 @ Wih^T                    [JB, 768pad->720]  K=256
// MODE 2: O1  = split(relu(A2@Wo1^T+b)*mask2) [JB, 512]          K=256
// MODE 3: ens = xpred + (O1@Wo2^T + b2).inno  [JB, 128]          K=512
#define STAGE_BYTES 40960          // 4 * 128 * 80
#define ARR_BYTES   10240
#define GEMM_SMEM   (2 * STAGE_BYTES + 512)

template <int MODE>
__global__ __launch_bounds__(256, 1)
void gemm_mma(const float* __restrict__ bias,   // M2: b_out1, M3: b_out2
              const float* __restrict__ u2,     // M2 only
              float* __restrict__ ens) {        // M3 only
    constexpr int KA = (MODE == 3) ? 512 : KPAD;
    constexpr int NKT = KA / 32;

    const __nv_bfloat16* pAh = (MODE == 1) ? g_A1h : ((MODE == 2) ? g_A2h : g_O1h);
    const __nv_bfloat16* pAl = (MODE == 1) ? g_A1l : ((MODE == 2) ? g_A2l : g_O1l);
    const __nv_bfloat16* pBh = (MODE == 1) ? g_Wihh : ((MODE == 2) ? g_Wo1h : g_Wo2h);
    const __nv_bfloat16* pBl = (MODE == 1) ? g_Wihl : ((MODE == 2) ? g_Wo1l : g_Wo2l);

    extern __shared__ char smem[];
    float* biasS = reinterpret_cast<float*>(smem + 2 * STAGE_BYTES);
    const uint32_t sb = smem_u32(smem);
    const int tid = threadIdx.x;
    const int lane = tid & 31, wid = tid >> 5;
    const int wm = wid & 1, wn = wid >> 1;
    const int m0 = blockIdx.y * 128, n0 = blockIdx.x * 128;

    if (MODE != 1 && tid < 128) biasS[tid] = bias[n0 + tid];

    // per-thread cp.async slots: id in [0,512): r=id>>2 (row), c=id&3 (16B chunk)
    const int r0c = tid >> 2, c0c = tid & 3;
    const int r1c = (tid + 256) >> 2, c1c = c0c;

    auto prefetch = [&](int kt) {
        uint32_t stage = sb + (kt & 1) * STAGE_BYTES;
        int kh = kt * 32;
#pragma unroll
        for (int q = 0; q < 2; q++) {
            int r = q ? r1c : r0c;
            int c = q ? c1c : c0c;
            uint32_t d = stage + r * 80 + c * 16;
            size_t ao = (size_t)(m0 + r) * KA + kh + c * 8;
            size_t bo = (size_t)(n0 + r) * KA + kh + c * 8;
            cpasync16(d,                 pAh + ao);
            cpasync16(d + ARR_BYTES,     pAl + ao);
            cpasync16(d + 2 * ARR_BYTES, pBh + bo);
            cpasync16(d + 3 * ARR_BYTES, pBl + bo);
        }
    };

    float c[4][4][4];
#pragma unroll
    for (int i = 0; i < 4; i++)
#pragma unroll
        for (int j = 0; j < 4; j++)
#pragma unroll
            for (int q = 0; q < 4; q++) c[i][j][q] = 0.f;

    prefetch(0);
    asm volatile("cp.async.commit_group;");

    for (int kt = 0; kt < NKT; kt++) {
        if (kt + 1 < NKT) {
            prefetch(kt + 1);
            asm volatile("cp.async.commit_group;");
            asm volatile("cp.async.wait_group 1;");
        } else {
            asm volatile("cp.async.wait_group 0;");
        }
        __syncthreads();
        uint32_t stage = sb + (kt & 1) * STAGE_BYTES;
#pragma unroll
        for (int s = 0; s < 2; s++) {
            uint32_t ah[4][4], al[4][4], bh[2][4], bl[2][4];
            uint32_t acol = ((lane >> 4) << 4) + s * 32;
#pragma unroll
            for (int mt = 0; mt < 4; mt++) {
                int rowA = wm * 64 + mt * 16 + (lane & 15);
                uint32_t ad = stage + rowA * 80 + acol;
                ldsm4(ah[mt], ad);
                ldsm4(al[mt], ad + ARR_BYTES);
            }
            uint32_t bcol = (((lane >> 3) & 1) << 4) + s * 32;
#pragma unroll
            for (int np = 0; np < 2; np++) {
                int rowB = wn * 32 + np * 16 + ((lane >> 4) << 3) + (lane & 7);
                uint32_t bd = stage + 2 * ARR_BYTES + rowB * 80 + bcol;
                ldsm4(bh[np], bd);
                ldsm4(bl[np], bd + ARR_BYTES);
            }
#pragma unroll
            for (int mt = 0; mt < 4; mt++)
#pragma unroll
                for (int nt = 0; nt < 4; nt++) {
                    const uint32_t* bhf = &bh[nt >> 1][(nt & 1) * 2];
                    const uint32_t* blf = &bl[nt >> 1][(nt & 1) * 2];
                    mma16816(c[mt][nt], ah[mt], bhf);
                    mma16816(c[mt][nt], ah[mt], blf);
                    mma16816(c[mt][nt], al[mt], bhf);
                }
        }
        __syncthreads();
    }

    // ---------------- epilogues ----------------
    const int g = lane >> 2, tg = lane & 3;
    if (MODE == 1) {
#pragma unroll
        for (int mt = 0; mt < 4; mt++) {
            int row = m0 + wm * 64 + mt * 16 + g;
#pragma unroll
            for (int nt = 0; nt < 4; nt++) {
                int gn = n0 + wn * 32 + nt * 8;
                if (gn < 720) {
                    int col = gn + tg * 2;
                    *reinterpret_cast<float2*>(g_gx + (size_t)row * 720 + col) =
                        make_float2(c[mt][nt][0], c[mt][nt][1]);
                    *reinterpret_cast<float2*>(g_gx + (size_t)(row + 8) * 720 + col) =
                        make_float2(c[mt][nt][2], c[mt][nt][3]);
                }
            }
        }
    } else if (MODE == 2) {
#pragma unroll
        for (int mt = 0; mt < 4; mt++) {
#pragma unroll
            for (int half = 0; half < 2; half++) {
                int row = m0 + wm * 64 + mt * 16 + g + half * 8;
#pragma unroll
                for (int nt = 0; nt < 4; nt++) {
                    int colL = wn * 32 + nt * 8 + tg * 2;   // local col in [0,128)
                    int col = n0 + colL;
                    float2 u = *reinterpret_cast<const float2*>(u2 + (size_t)row * OUT_HID + col);
                    float t0 = fmaxf(c[mt][nt][2 * half + 0] + biasS[colL], 0.f);
                    float t1 = fmaxf(c[mt][nt][2 * half + 1] + biasS[colL + 1], 0.f);
                    float v0 = (u.x > 0.65f) ? t0 * (1.0f / 0.35f) : 0.f;
                    float v1 = (u.y > 0.65f) ? t1 * (1.0f / 0.35f) : 0.f;
                    __nv_bfloat16 h0, l0, h1, l1;
                    fsplit(v0, h0, l0);
                    fsplit(v1, h1, l1);
                    __nv_bfloat162 hp; hp.x = h0; hp.y = h1;
                    __nv_bfloat162 lp; lp.x = l0; lp.y = l1;
                    *reinterpret_cast<__nv_bfloat162*>(g_O1h + (size_t)row * OUT_HID + col) = hp;
                    *reinterpret_cast<__nv_bfloat162*>(g_O1l + (size_t)row * OUT_HID + col) = lp;
                }
            }
        }
    } else {  // MODE 3: n index = s*8+o; warp covers s = wn*4+nt, o = tg*2,+1
#pragma unroll
        for (int mt = 0; mt < 4; mt++) {
#pragma unroll
            for (int half = 0; half < 2; half++) {
                int row = m0 + wm * 64 + mt * 16 + g + half * 8;
                int b = row & (B_DIM - 1);
                int j = row >> 12;
                float2 iv = *reinterpret_cast<const float2*>(g_inno + b * O_DIM + tg * 2);
#pragma unroll
                for (int nt = 0; nt < 4; nt++) {
                    int colL = wn * 32 + nt * 8 + tg * 2;
                    float v = (c[mt][nt][2 * half + 0] + biasS[colL]) * iv.x
                            + (c[mt][nt][2 * half + 1] + biasS[colL + 1]) * iv.y;
                    v += __shfl_xor_sync(0xffffffffu, v, 1);
                    v += __shfl_xor_sync(0xffffffffu, v, 2);
                    if (tg == 0) {
                        int s = wn * 4 + nt;
                        ens[(size_t)b * (J_DIM * S_DIM) + j * S_DIM + s] =
                            g_xpred[b * S_DIM + s] + v;
                    }
                }
            }
        }
    }
}

// ---------------- mean / unbiased var over J --------------------------------
__global__ void reduce_kernel(const float* __restrict__ ens, float* __restrict__ out) {
    int idx = blockIdx.x * blockDim.x + threadIdx.x;
    if (idx >= B_DIM * S_DIM) return;
    int b = idx >> 4, s = idx & 15;
    const float* p = ens + (size_t)b * (J_DIM * S_DIM) + s;
    float v[J_DIM], sum = 0.f;
#pragma unroll
    for (int j = 0; j < J_DIM; j++) { v[j] = p[j * S_DIM]; sum += v[j]; }
    float mean = sum * (1.0f / J_DIM);
    float var = 0.f;
#pragma unroll
    for (int j = 0; j < J_DIM; j++) { float d = v[j] - mean; var = fmaf(d, d, var); }
    out[idx] = mean;
    out[B_DIM * S_DIM + idx] = var * (1.0f / (J_DIM - 1));
}

// ---------------- launcher --------------------------------------------------
extern "C" void kernel_launch(void* const* d_in, const int* in_sizes, int n_in,
                              void* d_out, int out_size) {
    const float* y_t    = (const float*)d_in[0];
    const float* xprev  = (const float*)d_in[1];
    const float* F      = (const float*)d_in[2];
    const float* H      = (const float*)d_in[3];
    const float* W_fc   = (const float*)d_in[4];
    const float* b_fc   = (const float*)d_in[5];
    const float* W_ih   = (const float*)d_in[6];
    const float* W_hh   = (const float*)d_in[7];
    const float* b_ih   = (const float*)d_in[8];
    const float* b_hh   = (const float*)d_in[9];
    const float* W_out1 = (const float*)d_in[10];
    const float* b_out1 = (const float*)d_in[11];
    const float* W_out2 = (const float*)d_in[12];
    const float* b_out2 = (const float*)d_in[13];
    const float* h_init = (const float*)d_in[14];
    const float* u1     = (const float*)d_in[15];
    const float* u2     = (const float*)d_in[16];

    float* out = (float*)d_out;
    float* ens = out + 2 * B_DIM * S_DIM + 1;

    cudaFuncSetAttribute((const void*)gemm_mma<1>, cudaFuncAttributeMaxDynamicSharedMemorySize, GEMM_SMEM);
    cudaFuncSetAttribute((const void*)gemm_mma<2>, cudaFuncAttributeMaxDynamicSharedMemorySize, GEMM_SMEM);
    cudaFuncSetAttribute((const void*)gemm_mma<3>, cudaFuncAttributeMaxDynamicSharedMemorySize, GEMM_SMEM);

    gh_kernel<<<3, 256>>>(W_hh, b_hh, h_init, out);
    prep_kernel<<<B_DIM, 256>>>(y_t, xprev, F, H, W_fc, b_fc);
    convW_kernel<<<(768 * KPAD + 512 * KPAD + 128 * 512 + 255) / 256, 256>>>(W_ih, W_out1, W_out2);
    conv1_kernel<<<(JB * 64) / 256, 256>>>(u1);

    // G1: gx = A1 @ Wih^T   [JB, 720 (pad 768)]
    gemm_mma<1><<<dim3(6, JB / 128), 256, GEMM_SMEM>>>(nullptr, nullptr, nullptr);

    // GRU pointwise fused into A2 conversion
    conv2_kernel<<<(JB * 64) / 256, 256>>>(b_ih, h_init);

    // G2: O1 = split(relu(A2 @ Wo1^T + b) * mask2)
    gemm_mma<2><<<dim3(4, JB / 128), 256, GEMM_SMEM>>>(b_out1, u2, nullptr);

    // G3: ensemble = xpred + (O1 @ Wo2^T + b2) . inno
    gemm_mma<3><<<dim3(1, JB / 128), 256, GEMM_SMEM>>>(b_out2, nullptr, ens);

    reduce_kernel<<<(B_DIM * S_DIM) / 256, 256>>>(ens, out);
}

// round 4
// speedup vs baseline: 1.9351x; 1.0527x over previous
#include <cuda_runtime.h>
#include <cuda_bf16.h>
#include <cstdint>
#include <math.h>

// ---------------- problem dims ----------------------------------------------
#define B_DIM   4096
#define S_DIM   16
#define O_DIM   8
#define J_DIM   32
#define HID     240
#define OUT_HID 512
#define JB      (J_DIM * B_DIM)      // 131072
#define KPAD    256

// ---------------- scratch (device globals) ----------------------------------
__device__ float g_gh[3 * HID];
__device__ float g_bperm[768];                           // permuted b_ih(+g_gh) bias
__device__ float g_xpred[B_DIM * S_DIM];
__device__ float g_inno[B_DIM * O_DIM];
__device__ float g_xin[B_DIM * HID];

__device__ __nv_bfloat16 g_A2h[(size_t)JB * KPAD];       // h_new split
__device__ __nv_bfloat16 g_A2l[(size_t)JB * KPAD];
__device__ __nv_bfloat16 g_O1h[(size_t)JB * OUT_HID];    // o1 split
__device__ __nv_bfloat16 g_O1l[(size_t)JB * OUT_HID];
__device__ __nv_bfloat16 g_Wph[768 * KPAD], g_Wpl[768 * KPAD];   // permuted W_ih
__device__ __nv_bfloat16 g_Wo1h[512 * KPAD], g_Wo1l[512 * KPAD];
__device__ __nv_bfloat16 g_Wo2h[128 * 512],  g_Wo2l[128 * 512];

// ---------------- helpers ----------------------------------------------------
__device__ __forceinline__ uint32_t smem_u32(const void* p) {
    uint32_t a;
    asm("{ .reg .u64 t; cvta.to.shared.u64 t, %1; cvt.u32.u64 %0, t; }" : "=r"(a) : "l"(p));
    return a;
}
__device__ __forceinline__ void ldsm4(uint32_t* r, uint32_t addr) {
    asm volatile("ldmatrix.sync.aligned.m8n8.x4.shared.b16 {%0,%1,%2,%3}, [%4];"
                 : "=r"(r[0]), "=r"(r[1]), "=r"(r[2]), "=r"(r[3]) : "r"(addr));
}
__device__ __forceinline__ void mma16816(float* c, const uint32_t* a, const uint32_t* b) {
    asm volatile(
        "mma.sync.aligned.m16n8k16.row.col.f32.bf16.bf16.f32 "
        "{%0,%1,%2,%3}, {%4,%5,%6,%7}, {%8,%9}, {%0,%1,%2,%3};"
        : "+f"(c[0]), "+f"(c[1]), "+f"(c[2]), "+f"(c[3])
        : "r"(a[0]), "r"(a[1]), "r"(a[2]), "r"(a[3]), "r"(b[0]), "r"(b[1]));
}
__device__ __forceinline__ void cpasync16(uint32_t dst, const void* src) {
    asm volatile("cp.async.cg.shared.global [%0], [%1], 16;" :: "r"(dst), "l"(src));
}
__device__ __forceinline__ float fsig(float x) {
    float e, r;
    asm("ex2.approx.ftz.f32 %0, %1;" : "=f"(e) : "f"(-x * 1.4426950408889634f));
    asm("rcp.approx.ftz.f32 %0, %1;" : "=f"(r) : "f"(1.0f + e));
    return r;
}
__device__ __forceinline__ float ftanh_(float x) { return 2.0f * fsig(2.0f * x) - 1.0f; }
__device__ __forceinline__ void fsplit(float v, __nv_bfloat16& h, __nv_bfloat16& l) {
    h = __float2bfloat16_rn(v);
    l = __float2bfloat16_rn(v - __bfloat162float(h));
}

// ---------------- K0: gh + reg scalar ---------------------------------------
__global__ void gh_kernel(const float* __restrict__ W_hh, const float* __restrict__ b_hh,
                          const float* __restrict__ h_init, float* __restrict__ out) {
    int n = blockIdx.x * blockDim.x + threadIdx.x;
    if (n < 3 * HID) {
        float acc = b_hh[n];
        const float* w = W_hh + n * HID;
#pragma unroll 8
        for (int k = 0; k < HID; k++) acc = fmaf(h_init[k], w[k], acc);
        g_gh[n] = acc;
    }
    if (n == 0) {
        const float p1 = 0.5f, p2 = 0.65f;
        out[2 * B_DIM * S_DIM] =
            -(p1 * logf(p1) + (1.0f - p1) * logf(1.0f - p1))
            - (p2 * logf(p2) + (1.0f - p2) * logf(1.0f - p2));
    }
}

// permuted combined bias: chunk layout [r(40) | z(40) | n(40) | pad(8)] x 6
__global__ void bprep_kernel(const float* __restrict__ b_ih) {
    int n = blockIdx.x * blockDim.x + threadIdx.x;
    if (n >= 768) return;
    int c = n >> 7, w = n & 127;
    float v = 0.f;
    if (w < 120) {
        int gate = w / 40, t = w % 40;
        int orig = gate * 240 + c * 40 + t;
        v = b_ih[orig] + (gate < 2 ? g_gh[orig] : 0.f);
    }
    g_bperm[n] = v;
}

// ---------------- K1: per-b prep --------------------------------------------
__global__ void prep_kernel(const float* __restrict__ y_t, const float* __restrict__ xprev,
                            const float* __restrict__ F, const float* __restrict__ H,
                            const float* __restrict__ W_fc, const float* __restrict__ b_fc) {
    int b = blockIdx.x;
    int t = threadIdx.x;
    __shared__ float xp[S_DIM], si[S_DIM], inn[O_DIM];
    if (t < S_DIM) {
        float acc = 0.f;
        const float* fr = F + t * S_DIM;
#pragma unroll
        for (int k = 0; k < S_DIM; k++) acc = fmaf(xprev[b * S_DIM + k], fr[k], acc);
        xp[t] = acc;
        si[t] = xprev[b * S_DIM + t] - acc;
        g_xpred[b * S_DIM + t] = acc;
    }
    __syncthreads();
    if (t < O_DIM) {
        float acc = 0.f;
        const float* hr = H + t * S_DIM;
#pragma unroll
        for (int s = 0; s < S_DIM; s++) acc = fmaf(xp[s], hr[s], acc);
        float iv = y_t[b * O_DIM + t] - acc;
        inn[t] = iv;
        g_inno[b * O_DIM + t] = iv;
    }
    __syncthreads();
    if (t < HID) {
        const float* w = W_fc + t * 48;
        float acc = b_fc[t];
#pragma unroll
        for (int s = 0; s < S_DIM; s++) acc = fmaf(si[s], w[s], acc);
#pragma unroll
        for (int o = 0; o < O_DIM; o++) acc = fmaf(inn[o], w[16 + o] + w[40 + o], acc);
        g_xin[b * HID + t] = fmaxf(acc, 0.0f);
    }
}

// ---------------- weight conversion (permuted Wih, split bf16) ---------------
__global__ void convW_kernel(const float* __restrict__ W_ih,
                             const float* __restrict__ W_o1,
                             const float* __restrict__ W_o2) {
    int g = blockIdx.x * blockDim.x + threadIdx.x;
    const int N1 = 768 * KPAD, N2 = 512 * KPAD, N3 = 128 * 512;
    if (g < N1) {
        int n = g >> 8, k = g & 255;
        int c = n >> 7, w = n & 127;
        float v = 0.f;
        if (w < 120 && k < 240) {
            int gate = w / 40, t = w % 40;
            v = W_ih[(gate * 240 + c * 40 + t) * 240 + k];
        }
        fsplit(v, g_Wph[g], g_Wpl[g]);
    } else if (g < N1 + N2) {
        int i = g - N1;
        int k = i & 255;
        float v = (k < 240) ? W_o1[(i >> 8) * 240 + k] : 0.f;
        fsplit(v, g_Wo1h[i], g_Wo1l[i]);
    } else if (g < N1 + N2 + N3) {
        int i = g - N1 - N2;
        fsplit(W_o2[i], g_Wo2h[i], g_Wo2l[i]);
    }
}

// ---------------- fused A-resident GEMM -------------------------------------
// SMEM layout:
//   [0, 163840)          A resident: 2 arrays x 8 slabs x (128 rows x 80B)
//   [163840, 204800)     B staging: 2 stages x 2 arrays x 10240B
//                        (MODE 1 epilogue aliases this as 64x128 fp32 scratch)
//   [204800, 205312)     bias slice (128 floats)
#define ARES_ARR  81920
#define SLAB      10240
#define BOFF      163840
#define BSTAGE    20480
#define BIAS_OFF  204800
#define FUSED_SMEM 205312

// MODE 1: A=mask(u1)*xin (built in-kernel) @ Wperm^T -> GRU -> g_A2 split
// MODE 2: A=g_A2 (cp.async resident) @ Wo1^T -> relu+bias+mask(u2) -> g_O1 split
template <int MODE>
__global__ __launch_bounds__(256, 1)
void gemm_fused(const float* __restrict__ aux1,   // M1: u1      M2: b_out1
                const float* __restrict__ aux2)   // M1: h_init  M2: u2
{
    constexpr int NCHUNK = (MODE == 1) ? 6 : 4;
    const __nv_bfloat16* pBh = (MODE == 1) ? g_Wph : g_Wo1h;
    const __nv_bfloat16* pBl = (MODE == 1) ? g_Wpl : g_Wo1l;

    extern __shared__ char smem[];
    float* biasS = reinterpret_cast<float*>(smem + BIAS_OFF);
    const uint32_t sb = smem_u32(smem);
    const int tid = threadIdx.x;
    const int lane = tid & 31, wid = tid >> 5;
    const int wm = wid & 1, wn = wid >> 1;
    const int g = lane >> 2, tg = lane & 3;
    const int m0 = blockIdx.x * 128;

    // ---- build / load resident A tile ----
    if (MODE == 1) {
        // mask + split from u1 / g_xin directly into SMEM slabs
        for (int idx = tid; idx < 128 * 60; idx += 256) {
            int row = idx / 60, k4 = idx - row * 60;
            int k = 4 * k4;
            int b = (m0 + row) & (B_DIM - 1);
            float4 x = *reinterpret_cast<const float4*>(g_xin + b * HID + k);
            float4 u = *reinterpret_cast<const float4*>(aux1 + (size_t)(m0 + row) * HID + k);
            float v0 = (u.x > 0.5f) ? 2.0f * x.x : 0.f;
            float v1 = (u.y > 0.5f) ? 2.0f * x.y : 0.f;
            float v2 = (u.z > 0.5f) ? 2.0f * x.z : 0.f;
            float v3 = (u.w > 0.5f) ? 2.0f * x.w : 0.f;
            __nv_bfloat16 hh[4], ll[4];
            fsplit(v0, hh[0], ll[0]); fsplit(v1, hh[1], ll[1]);
            fsplit(v2, hh[2], ll[2]); fsplit(v3, hh[3], ll[3]);
            uint32_t off = (uint32_t)((k >> 5) * SLAB + row * 80 + (k & 31) * 2);
            *reinterpret_cast<uint2*>(smem + off) = *reinterpret_cast<uint2*>(hh);
            *reinterpret_cast<uint2*>(smem + ARES_ARR + off) = *reinterpret_cast<uint2*>(ll);
        }
        // zero pad cols 240..255 (slab 7, bytes 32..63 of each row)
        if (tid < 128) {
            uint32_t off = (uint32_t)(7 * SLAB + tid * 80 + 32);
            uint4 z = make_uint4(0, 0, 0, 0);
            *reinterpret_cast<uint4*>(smem + off) = z;
            *reinterpret_cast<uint4*>(smem + off + 16) = z;
            *reinterpret_cast<uint4*>(smem + ARES_ARR + off) = z;
            *reinterpret_cast<uint4*>(smem + ARES_ARR + off + 16) = z;
        }
    } else {
        // cp.async A2h/A2l into resident slabs (layout matches: 16B = 8 cols)
#pragma unroll
        for (int i = 0; i < 32; i++) {
            int id = tid + 256 * i;          // [0, 8192)
            int arr = id >> 12, rem = id & 4095;
            int row = rem >> 5, c0 = rem & 31;   // c0: 16B chunk (8 cols)
            uint32_t dst = sb + arr * ARES_ARR + (c0 >> 2) * SLAB + row * 80 + (c0 & 3) * 16;
            const __nv_bfloat16* src = (arr ? g_A2l : g_A2h) + (size_t)(m0 + row) * KPAD + c0 * 8;
            cpasync16(dst, src);
        }
        asm volatile("cp.async.commit_group;");
    }

    // per-thread B prefetch slots: 512 slots = 128 rows x 4 x 16B
    const int r0c = tid >> 2, c0c = tid & 3;
    const int r1c = (tid + 256) >> 2;

    for (int c = 0; c < NCHUNK; c++) {
        const int n0 = c * 128;
        if (tid < 128)
            biasS[tid] = (MODE == 1) ? g_bperm[n0 + tid] : aux1[n0 + tid];

        auto prefetchB = [&](int kt) {
            uint32_t stage = sb + BOFF + (kt & 1) * BSTAGE;
            int kh = kt * 32;
#pragma unroll
            for (int q = 0; q < 2; q++) {
                int r = q ? r1c : r0c;
                uint32_t d = stage + r * 80 + c0c * 16;
                size_t bo = (size_t)(n0 + r) * KPAD + kh + c0c * 8;
                cpasync16(d, pBh + bo);
                cpasync16(d + SLAB, pBl + bo);
            }
        };

        float acc[4][4][4];
#pragma unroll
        for (int i = 0; i < 4; i++)
#pragma unroll
            for (int j = 0; j < 4; j++)
#pragma unroll
                for (int q = 0; q < 4; q++) acc[i][j][q] = 0.f;

        prefetchB(0);
        asm volatile("cp.async.commit_group;");

        for (int kt = 0; kt < 8; kt++) {
            if (kt + 1 < 8) {
                prefetchB(kt + 1);
                asm volatile("cp.async.commit_group;");
                asm volatile("cp.async.wait_group 1;");
            } else {
                asm volatile("cp.async.wait_group 0;");
            }
            __syncthreads();
            uint32_t stageB = sb + BOFF + (kt & 1) * BSTAGE;
            uint32_t slabA = sb + kt * SLAB;
#pragma unroll
            for (int s = 0; s < 2; s++) {
                uint32_t ah[4][4], al[4][4], bh[2][4], bl[2][4];
                uint32_t acol = ((lane >> 4) << 4) + s * 32;
#pragma unroll
                for (int mt = 0; mt < 4; mt++) {
                    int rowA = wm * 64 + mt * 16 + (lane & 15);
                    uint32_t ad = slabA + rowA * 80 + acol;
                    ldsm4(ah[mt], ad);
                    ldsm4(al[mt], ad + ARES_ARR);
                }
                uint32_t bcol = (((lane >> 3) & 1) << 4) + s * 32;
#pragma unroll
                for (int np = 0; np < 2; np++) {
                    int rowB = wn * 32 + np * 16 + ((lane >> 4) << 3) + (lane & 7);
                    uint32_t bd = stageB + rowB * 80 + bcol;
                    ldsm4(bh[np], bd);
                    ldsm4(bl[np], bd + SLAB);
                }
#pragma unroll
                for (int mt = 0; mt < 4; mt++)
#pragma unroll
                    for (int nt = 0; nt < 4; nt++) {
                        const uint32_t* bhf = &bh[nt >> 1][(nt & 1) * 2];
                        const uint32_t* blf = &bl[nt >> 1][(nt & 1) * 2];
                        mma16816(acc[mt][nt], ah[mt], bhf);
                        mma16816(acc[mt][nt], ah[mt], blf);
                        mma16816(acc[mt][nt], al[mt], bhf);
                    }
            }
            __syncthreads();
        }

        // ---------------- epilogues ----------------
        if (MODE == 1) {
            // GRU over chunk cols [r(40)|z(40)|n(40)]: SMEM exchange in B staging
            float* scr = reinterpret_cast<float*>(smem + BOFF);  // 64 x 128 fp32
#pragma unroll
            for (int p = 0; p < 2; p++) {
                if (wm == p) {
#pragma unroll
                    for (int mt = 0; mt < 4; mt++)
#pragma unroll
                        for (int half = 0; half < 2; half++) {
                            int lr = mt * 16 + g + half * 8;
#pragma unroll
                            for (int nt = 0; nt < 4; nt++) {
                                int colL = wn * 32 + nt * 8 + tg * 2;
                                scr[lr * 128 + colL] = acc[mt][nt][2 * half + 0];
                                scr[lr * 128 + colL + 1] = acc[mt][nt][2 * half + 1];
                            }
                        }
                }
                __syncthreads();
                // 64 rows x 20 h-pairs
#pragma unroll
                for (int it = 0; it < 5; it++) {
                    int item = tid + 256 * it;          // [0,1280)
                    int lr = item / 20, h2 = (item - lr * 20) * 2;
                    int row = m0 + p * 64 + lr;
                    __nv_bfloat16 hh[2], ll[2];
#pragma unroll
                    for (int e = 0; e < 2; e++) {
                        int h = h2 + e;
                        int hp = c * 40 + h;
                        float pre_r = scr[lr * 128 + h] + biasS[h];
                        float pre_z = scr[lr * 128 + 40 + h] + biasS[40 + h];
                        float pre_n = scr[lr * 128 + 80 + h] + biasS[80 + h];
                        float r = fsig(pre_r);
                        float z = fsig(pre_z);
                        float nn = ftanh_(pre_n + r * g_gh[480 + hp]);
                        float hv = (1.0f - z) * nn + z * aux2[hp];
                        fsplit(hv, hh[e], ll[e]);
                    }
                    size_t o = (size_t)row * KPAD + c * 40 + h2;
                    *reinterpret_cast<uint32_t*>(g_A2h + o) = *reinterpret_cast<uint32_t*>(hh);
                    *reinterpret_cast<uint32_t*>(g_A2l + o) = *reinterpret_cast<uint32_t*>(ll);
                }
                __syncthreads();
            }
        } else {
#pragma unroll
            for (int mt = 0; mt < 4; mt++)
#pragma unroll
                for (int half = 0; half < 2; half++) {
                    int row = m0 + wm * 64 + mt * 16 + g + half * 8;
#pragma unroll
                    for (int nt = 0; nt < 4; nt++) {
                        int colL = wn * 32 + nt * 8 + tg * 2;
                        int col = n0 + colL;
                        float2 u = *reinterpret_cast<const float2*>(
                            aux2 + (size_t)row * OUT_HID + col);
                        float t0 = fmaxf(acc[mt][nt][2 * half + 0] + biasS[colL], 0.f);
                        float t1 = fmaxf(acc[mt][nt][2 * half + 1] + biasS[colL + 1], 0.f);
                        float v0 = (u.x > 0.65f) ? t0 * (1.0f / 0.35f) : 0.f;
                        float v1 = (u.y > 0.65f) ? t1 * (1.0f / 0.35f) : 0.f;
                        __nv_bfloat16 h0, l0, h1, l1;
                        fsplit(v0, h0, l0);
                        fsplit(v1, h1, l1);
                        __nv_bfloat162 hp; hp.x = h0; hp.y = h1;
                        __nv_bfloat162 lp; lp.x = l0; lp.y = l1;
                        *reinterpret_cast<__nv_bfloat162*>(g_O1h + (size_t)row * OUT_HID + col) = hp;
                        *reinterpret_cast<__nv_bfloat162*>(g_O1l + (size_t)row * OUT_HID + col) = lp;
                    }
                }
            __syncthreads();
        }
    }
}

// ---------------- G3: streaming split-bf16 GEMM (K=512, N=128) --------------
#define STAGE3 40960
#define ARR3   10240
#define G3_SMEM (2 * STAGE3 + 512)

__global__ __launch_bounds__(256, 1)
void gemm_g3(const float* __restrict__ bias, float* __restrict__ ens) {
    constexpr int KA = 512;
    constexpr int NKT = KA / 32;

    extern __shared__ char smem[];
    float* biasS = reinterpret_cast<float*>(smem + 2 * STAGE3);
    const uint32_t sb = smem_u32(smem);
    const int tid = threadIdx.x;
    const int lane = tid & 31, wid = tid >> 5;
    const int wm = wid & 1, wn = wid >> 1;
    const int m0 = blockIdx.y * 128;

    if (tid < 128) biasS[tid] = bias[tid];

    const int r0c = tid >> 2, c0c = tid & 3;
    const int r1c = (tid + 256) >> 2;

    auto prefetch = [&](int kt) {
        uint32_t stage = sb + (kt & 1) * STAGE3;
        int kh = kt * 32;
#pragma unroll
        for (int q = 0; q < 2; q++) {
            int r = q ? r1c : r0c;
            uint32_t d = stage + r * 80 + c0c * 16;
            size_t ao = (size_t)(m0 + r) * KA + kh + c0c * 8;
            size_t bo = (size_t)r * KA + kh + c0c * 8;
            cpasync16(d,            g_O1h + ao);
            cpasync16(d + ARR3,     g_O1l + ao);
            cpasync16(d + 2 * ARR3, g_Wo2h + bo);
            cpasync16(d + 3 * ARR3, g_Wo2l + bo);
        }
    };

    float c[4][4][4];
#pragma unroll
    for (int i = 0; i < 4; i++)
#pragma unroll
        for (int j = 0; j < 4; j++)
#pragma unroll
            for (int q = 0; q < 4; q++) c[i][j][q] = 0.f;

    prefetch(0);
    asm volatile("cp.async.commit_group;");

    for (int kt = 0; kt < NKT; kt++) {
        if (kt + 1 < NKT) {
            prefetch(kt + 1);
            asm volatile("cp.async.commit_group;");
            asm volatile("cp.async.wait_group 1;");
        } else {
            asm volatile("cp.async.wait_group 0;");
        }
        __syncthreads();
        uint32_t stage = sb + (kt & 1) * STAGE3;
#pragma unroll
        for (int s = 0; s < 2; s++) {
            uint32_t ah[4][4], al[4][4], bh[2][4], bl[2][4];
            uint32_t acol = ((lane >> 4) << 4) + s * 32;
#pragma unroll
            for (int mt = 0; mt < 4; mt++) {
                int rowA = wm * 64 + mt * 16 + (lane & 15);
                uint32_t ad = stage + rowA * 80 + acol;
                ldsm4(ah[mt], ad);
                ldsm4(al[mt], ad + ARR3);
            }
            uint32_t bcol = (((lane >> 3) & 1) << 4) + s * 32;
#pragma unroll
            for (int np = 0; np < 2; np++) {
                int rowB = wn * 32 + np * 16 + ((lane >> 4) << 3) + (lane & 7);
                uint32_t bd = stage + 2 * ARR3 + rowB * 80 + bcol;
                ldsm4(bh[np], bd);
                ldsm4(bl[np], bd + ARR3);
            }
#pragma unroll
            for (int mt = 0; mt < 4; mt++)
#pragma unroll
                for (int nt = 0; nt < 4; nt++) {
                    const uint32_t* bhf = &bh[nt >> 1][(nt & 1) * 2];
                    const uint32_t* blf = &bl[nt >> 1][(nt & 1) * 2];
                    mma16816(c[mt][nt], ah[mt], bhf);
                    mma16816(c[mt][nt], ah[mt], blf);
                    mma16816(c[mt][nt], al[mt], bhf);
                }
        }
        __syncthreads();
    }

    const int g = lane >> 2, tg = lane & 3;
#pragma unroll
    for (int mt = 0; mt < 4; mt++) {
#pragma unroll
        for (int half = 0; half < 2; half++) {
            int row = m0 + wm * 64 + mt * 16 + g + half * 8;
            int b = row & (B_DIM - 1);
            int j = row >> 12;
            float2 iv = *reinterpret_cast<const float2*>(g_inno + b * O_DIM + tg * 2);
#pragma unroll
            for (int nt = 0; nt < 4; nt++) {
                int colL = wn * 32 + nt * 8 + tg * 2;
                float v = (c[mt][nt][2 * half + 0] + biasS[colL]) * iv.x
                        + (c[mt][nt][2 * half + 1] + biasS[colL + 1]) * iv.y;
                v += __shfl_xor_sync(0xffffffffu, v, 1);
                v += __shfl_xor_sync(0xffffffffu, v, 2);
                if (tg == 0) {
                    int s = wn * 4 + nt;
                    ens[(size_t)b * (J_DIM * S_DIM) + j * S_DIM + s] =
                        g_xpred[b * S_DIM + s] + v;
                }
            }
        }
    }
}

// ---------------- mean / unbiased var over J --------------------------------
__global__ void reduce_kernel(const float* __restrict__ ens, float* __restrict__ out) {
    int idx = blockIdx.x * blockDim.x + threadIdx.x;
    if (idx >= B_DIM * S_DIM) return;
    int b = idx >> 4, s = idx & 15;
    const float* p = ens + (size_t)b * (J_DIM * S_DIM) + s;
    float v[J_DIM], sum = 0.f;
#pragma unroll
    for (int j = 0; j < J_DIM; j++) { v[j] = p[j * S_DIM]; sum += v[j]; }
    float mean = sum * (1.0f / J_DIM);
    float var = 0.f;
#pragma unroll
    for (int j = 0; j < J_DIM; j++) { float d = v[j] - mean; var = fmaf(d, d, var); }
    out[idx] = mean;
    out[B_DIM * S_DIM + idx] = var * (1.0f / (J_DIM - 1));
}

// ---------------- launcher --------------------------------------------------
extern "C" void kernel_launch(void* const* d_in, const int* in_sizes, int n_in,
                              void* d_out, int out_size) {
    const float* y_t    = (const float*)d_in[0];
    const float* xprev  = (const float*)d_in[1];
    const float* F      = (const float*)d_in[2];
    const float* H      = (const float*)d_in[3];
    const float* W_fc   = (const float*)d_in[4];
    const float* b_fc   = (const float*)d_in[5];
    const float* W_ih   = (const float*)d_in[6];
    const float* W_hh   = (const float*)d_in[7];
    const float* b_ih   = (const float*)d_in[8];
    const float* b_hh   = (const float*)d_in[9];
    const float* W_out1 = (const float*)d_in[10];
    const float* b_out1 = (const float*)d_in[11];
    const float* W_out2 = (const float*)d_in[12];
    const float* b_out2 = (const float*)d_in[13];
    const float* h_init = (const float*)d_in[14];
    const float* u1     = (const float*)d_in[15];
    const float* u2     = (const float*)d_in[16];

    float* out = (float*)d_out;
    float* ens = out + 2 * B_DIM * S_DIM + 1;

    cudaFuncSetAttribute((const void*)gemm_fused<1>, cudaFuncAttributeMaxDynamicSharedMemorySize, FUSED_SMEM);
    cudaFuncSetAttribute((const void*)gemm_fused<2>, cudaFuncAttributeMaxDynamicSharedMemorySize, FUSED_SMEM);
    cudaFuncSetAttribute((const void*)gemm_g3, cudaFuncAttributeMaxDynamicSharedMemorySize, G3_SMEM);

    gh_kernel<<<3, 256>>>(W_hh, b_hh, h_init, out);
    bprep_kernel<<<3, 256>>>(b_ih);
    prep_kernel<<<B_DIM, 256>>>(y_t, xprev, F, H, W_fc, b_fc);
    convW_kernel<<<(768 * KPAD + 512 * KPAD + 128 * 512 + 255) / 256, 256>>>(W_ih, W_out1, W_out2);

    // G1 + GRU fused: builds A from u1/xin, 6 n-chunks, GRU epilogue -> A2
    gemm_fused<1><<<JB / 128, 256, FUSED_SMEM>>>(u1, h_init);

    // G2: A2-resident, 4 n-chunks -> O1 split
    gemm_fused<2><<<JB / 128, 256, FUSED_SMEM>>>(b_out1, u2);

    // G3: ensemble = xpred + (O1 @ Wo2^T + b2) . inno
    gemm_g3<<<dim3(1, JB / 128), 256, G3_SMEM>>>(b_out2, ens);

    reduce_kernel<<<(B_DIM * S_DIM) / 256, 256>>>(ens, out);
}

// round 5
// speedup vs baseline: 2.2928x; 1.1848x over previous
#include <cuda_runtime.h>
#include <cuda_bf16.h>
#include <cstdint>
#include <math.h>

// ---------------- problem dims ----------------------------------------------
#define B_DIM   4096
#define S_DIM   16
#define O_DIM   8
#define J_DIM   32
#define HID     240
#define OUT_HID 512
#define JB      (J_DIM * B_DIM)      // 131072
#define KPAD    256

// ---------------- scratch (device globals) ----------------------------------
__device__ float g_gh[3 * HID];
__device__ float g_bperm[768];
__device__ float g_xpred[B_DIM * S_DIM];
__device__ float g_inno[B_DIM * O_DIM];
__device__ float g_xin[B_DIM * HID];

__device__ __nv_bfloat16 g_A1h[(size_t)JB * KPAD];       // (xin*mask1) split
__device__ __nv_bfloat16 g_A1l[(size_t)JB * KPAD];
__device__ __nv_bfloat16 g_A2h[(size_t)JB * KPAD];       // h_new split
__device__ __nv_bfloat16 g_A2l[(size_t)JB * KPAD];
__device__ __nv_bfloat16 g_O1h[(size_t)JB * OUT_HID];    // o1 split
__device__ __nv_bfloat16 g_O1l[(size_t)JB * OUT_HID];
__device__ __nv_bfloat16 g_Wph[768 * KPAD], g_Wpl[768 * KPAD];   // permuted W_ih
__device__ __nv_bfloat16 g_Wo1h[512 * KPAD], g_Wo1l[512 * KPAD];
__device__ __nv_bfloat16 g_Wo2h[128 * 512],  g_Wo2l[128 * 512];

// ---------------- helpers ----------------------------------------------------
__device__ __forceinline__ uint32_t smem_u32(const void* p) {
    uint32_t a;
    asm("{ .reg .u64 t; cvta.to.shared.u64 t, %1; cvt.u32.u64 %0, t; }" : "=r"(a) : "l"(p));
    return a;
}
__device__ __forceinline__ void ldsm4(uint32_t* r, uint32_t addr) {
    asm volatile("ldmatrix.sync.aligned.m8n8.x4.shared.b16 {%0,%1,%2,%3}, [%4];"
                 : "=r"(r[0]), "=r"(r[1]), "=r"(r[2]), "=r"(r[3]) : "r"(addr));
}
__device__ __forceinline__ void mma16816(float* c, const uint32_t* a, const uint32_t* b) {
    asm volatile(
        "mma.sync.aligned.m16n8k16.row.col.f32.bf16.bf16.f32 "
        "{%0,%1,%2,%3}, {%4,%5,%6,%7}, {%8,%9}, {%0,%1,%2,%3};"
        : "+f"(c[0]), "+f"(c[1]), "+f"(c[2]), "+f"(c[3])
        : "r"(a[0]), "r"(a[1]), "r"(a[2]), "r"(a[3]), "r"(b[0]), "r"(b[1]));
}
__device__ __forceinline__ void cpasync16(uint32_t dst, const void* src) {
    asm volatile("cp.async.cg.shared.global [%0], [%1], 16;" :: "r"(dst), "l"(src));
}
__device__ __forceinline__ float fsig(float x) {
    float e, r;
    asm("ex2.approx.ftz.f32 %0, %1;" : "=f"(e) : "f"(-x * 1.4426950408889634f));
    asm("rcp.approx.ftz.f32 %0, %1;" : "=f"(r) : "f"(1.0f + e));
    return r;
}
__device__ __forceinline__ float ftanh_(float x) { return 2.0f * fsig(2.0f * x) - 1.0f; }
__device__ __forceinline__ void fsplit(float v, __nv_bfloat16& h, __nv_bfloat16& l) {
    h = __float2bfloat16_rn(v);
    l = __float2bfloat16_rn(v - __bfloat162float(h));
}

// ---------------- K0: gh + reg scalar ---------------------------------------
__global__ void gh_kernel(const float* __restrict__ W_hh, const float* __restrict__ b_hh,
                          const float* __restrict__ h_init, float* __restrict__ out) {
    int n = blockIdx.x * blockDim.x + threadIdx.x;
    if (n < 3 * HID) {
        float acc = b_hh[n];
        const float* w = W_hh + n * HID;
#pragma unroll 8
        for (int k = 0; k < HID; k++) acc = fmaf(h_init[k], w[k], acc);
        g_gh[n] = acc;
    }
    if (n == 0) {
        const float p1 = 0.5f, p2 = 0.65f;
        out[2 * B_DIM * S_DIM] =
            -(p1 * logf(p1) + (1.0f - p1) * logf(1.0f - p1))
            - (p2 * logf(p2) + (1.0f - p2) * logf(1.0f - p2));
    }
}

// permuted combined bias: chunk layout [r(40) | z(40) | n(40) | pad(8)] x 6
__global__ void bprep_kernel(const float* __restrict__ b_ih) {
    int n = blockIdx.x * blockDim.x + threadIdx.x;
    if (n >= 768) return;
    int c = n >> 7, w = n & 127;
    float v = 0.f;
    if (w < 120) {
        int gate = w / 40, t = w % 40;
        int orig = gate * 240 + c * 40 + t;
        v = b_ih[orig] + (gate < 2 ? g_gh[orig] : 0.f);
    }
    g_bperm[n] = v;
}

// ---------------- K1: per-b prep --------------------------------------------
__global__ void prep_kernel(const float* __restrict__ y_t, const float* __restrict__ xprev,
                            const float* __restrict__ F, const float* __restrict__ H,
                            const float* __restrict__ W_fc, const float* __restrict__ b_fc) {
    int b = blockIdx.x;
    int t = threadIdx.x;
    __shared__ float xp[S_DIM], si[S_DIM], inn[O_DIM];
    if (t < S_DIM) {
        float acc = 0.f;
        const float* fr = F + t * S_DIM;
#pragma unroll
        for (int k = 0; k < S_DIM; k++) acc = fmaf(xprev[b * S_DIM + k], fr[k], acc);
        xp[t] = acc;
        si[t] = xprev[b * S_DIM + t] - acc;
        g_xpred[b * S_DIM + t] = acc;
    }
    __syncthreads();
    if (t < O_DIM) {
        float acc = 0.f;
        const float* hr = H + t * S_DIM;
#pragma unroll
        for (int s = 0; s < S_DIM; s++) acc = fmaf(xp[s], hr[s], acc);
        float iv = y_t[b * O_DIM + t] - acc;
        inn[t] = iv;
        g_inno[b * O_DIM + t] = iv;
    }
    __syncthreads();
    if (t < HID) {
        const float* w = W_fc + t * 48;
        float acc = b_fc[t];
#pragma unroll
        for (int s = 0; s < S_DIM; s++) acc = fmaf(si[s], w[s], acc);
#pragma unroll
        for (int o = 0; o < O_DIM; o++) acc = fmaf(inn[o], w[16 + o] + w[40 + o], acc);
        g_xin[b * HID + t] = fmaxf(acc, 0.0f);
    }
}

// ---------------- weight conversion (permuted Wih, split bf16) ---------------
__global__ void convW_kernel(const float* __restrict__ W_ih,
                             const float* __restrict__ W_o1,
                             const float* __restrict__ W_o2) {
    int g = blockIdx.x * blockDim.x + threadIdx.x;
    const int N1 = 768 * KPAD, N2 = 512 * KPAD, N3 = 128 * 512;
    if (g < N1) {
        int n = g >> 8, k = g & 255;
        int c = n >> 7, w = n & 127;
        float v = 0.f;
        if (w < 120 && k < 240) {
            int gate = w / 40, t = w % 40;
            v = W_ih[(gate * 240 + c * 40 + t) * 240 + k];
        }
        fsplit(v, g_Wph[g], g_Wpl[g]);
    } else if (g < N1 + N2) {
        int i = g - N1;
        int k = i & 255;
        float v = (k < 240) ? W_o1[(i >> 8) * 240 + k] : 0.f;
        fsplit(v, g_Wo1h[i], g_Wo1l[i]);
    } else if (g < N1 + N2 + N3) {
        int i = g - N1 - N2;
        fsplit(W_o2[i], g_Wo2h[i], g_Wo2l[i]);
    }
}

// ---------------- conv1: A1 = split(xin * mask1) ----------------------------
__global__ void conv1_kernel(const float* __restrict__ u1) {
    int g = blockIdx.x * blockDim.x + threadIdx.x;   // row*64 + k4
    if (g >= JB * 64) return;
    int row = g >> 6, k4 = g & 63;
    __nv_bfloat16 hh[4], ll[4];
    if (k4 < 60) {
        int b = row & (B_DIM - 1);
        float4 x = *reinterpret_cast<const float4*>(g_xin + b * HID + 4 * k4);
        float4 u = *reinterpret_cast<const float4*>(u1 + (size_t)row * HID + 4 * k4);
        float v0 = (u.x > 0.5f) ? 2.0f * x.x : 0.f;
        float v1 = (u.y > 0.5f) ? 2.0f * x.y : 0.f;
        float v2 = (u.z > 0.5f) ? 2.0f * x.z : 0.f;
        float v3 = (u.w > 0.5f) ? 2.0f * x.w : 0.f;
        fsplit(v0, hh[0], ll[0]); fsplit(v1, hh[1], ll[1]);
        fsplit(v2, hh[2], ll[2]); fsplit(v3, hh[3], ll[3]);
    } else {
#pragma unroll
        for (int e = 0; e < 4; e++) { hh[e] = __float2bfloat16_rn(0.f); ll[e] = hh[e]; }
    }
    *reinterpret_cast<uint2*>(g_A1h + (size_t)row * KPAD + 4 * k4) = *reinterpret_cast<uint2*>(hh);
    *reinterpret_cast<uint2*>(g_A1l + (size_t)row * KPAD + 4 * k4) = *reinterpret_cast<uint2*>(ll);
}

// ---------------- streaming split-bf16 GEMM, 2 CTAs/SM ----------------------
// 128x128 block, BK=32, 8 warps (2m x 4n), warp tile 64x32, m16n8k16.
// MODE 1: permuted chunk -> GRU epilogue -> g_A2 split  [K=256, grid(6,1024)]
// MODE 2: O1 = split(relu(A2@Wo1^T+b)*mask2)            [K=256, grid(4,1024)]
// MODE 3: ens = xpred + (O1@Wo2^T + b2).inno            [K=512, grid(1,1024)]
#define STAGE_BYTES 40960          // 4 arrays x 128 rows x 80B
#define ARR_BYTES   10240
#define GEMM_SMEM   (2 * STAGE_BYTES + 512)

template <int MODE>
__global__ __launch_bounds__(256, 2)
void gemm_mma(const float* __restrict__ aux1,   // M2: b_out1, M3: b_out2
              const float* __restrict__ aux2,   // M1: h_init, M2: u2
              float* __restrict__ ens) {        // M3 only
    constexpr int KA = (MODE == 3) ? 512 : KPAD;
    constexpr int NKT = KA / 32;

    const __nv_bfloat16* pAh = (MODE == 1) ? g_A1h : ((MODE == 2) ? g_A2h : g_O1h);
    const __nv_bfloat16* pAl = (MODE == 1) ? g_A1l : ((MODE == 2) ? g_A2l : g_O1l);
    const __nv_bfloat16* pBh = (MODE == 1) ? g_Wph : ((MODE == 2) ? g_Wo1h : g_Wo2h);
    const __nv_bfloat16* pBl = (MODE == 1) ? g_Wpl : ((MODE == 2) ? g_Wo1l : g_Wo2l);

    extern __shared__ char smem[];
    float* biasS = reinterpret_cast<float*>(smem + 2 * STAGE_BYTES);
    const uint32_t sb = smem_u32(smem);
    const int tid = threadIdx.x;
    const int lane = tid & 31, wid = tid >> 5;
    const int wm = wid & 1, wn = wid >> 1;
    const int m0 = blockIdx.y * 128, n0 = blockIdx.x * 128;

    if (tid < 128)
        biasS[tid] = (MODE == 1) ? g_bperm[n0 + tid] : aux1[n0 + tid];

    const int r0c = tid >> 2, c0c = tid & 3;
    const int r1c = (tid + 256) >> 2;

    auto prefetch = [&](int kt) {
        uint32_t stage = sb + (kt & 1) * STAGE_BYTES;
        int kh = kt * 32;
#pragma unroll
        for (int q = 0; q < 2; q++) {
            int r = q ? r1c : r0c;
            uint32_t d = stage + r * 80 + c0c * 16;
            size_t ao = (size_t)(m0 + r) * KA + kh + c0c * 8;
            size_t bo = (MODE == 3) ? ((size_t)r * KA + kh + c0c * 8)
                                    : ((size_t)(n0 + r) * KA + kh + c0c * 8);
            cpasync16(d,                 pAh + ao);
            cpasync16(d + ARR_BYTES,     pAl + ao);
            cpasync16(d + 2 * ARR_BYTES, pBh + bo);
            cpasync16(d + 3 * ARR_BYTES, pBl + bo);
        }
    };

    float c[4][4][4];
#pragma unroll
    for (int i = 0; i < 4; i++)
#pragma unroll
        for (int j = 0; j < 4; j++)
#pragma unroll
            for (int q = 0; q < 4; q++) c[i][j][q] = 0.f;

    prefetch(0);
    asm volatile("cp.async.commit_group;");

    for (int kt = 0; kt < NKT; kt++) {
        if (kt + 1 < NKT) {
            prefetch(kt + 1);
            asm volatile("cp.async.commit_group;");
            asm volatile("cp.async.wait_group 1;");
        } else {
            asm volatile("cp.async.wait_group 0;");
        }
        __syncthreads();
        uint32_t stage = sb + (kt & 1) * STAGE_BYTES;
#pragma unroll
        for (int s = 0; s < 2; s++) {
            uint32_t bh[2][4], bl[2][4];
            uint32_t bcol = (((lane >> 3) & 1) << 4) + s * 32;
#pragma unroll
            for (int np = 0; np < 2; np++) {
                int rowB = wn * 32 + np * 16 + ((lane >> 4) << 3) + (lane & 7);
                uint32_t bd = stage + 2 * ARR_BYTES + rowB * 80 + bcol;
                ldsm4(bh[np], bd);
                ldsm4(bl[np], bd + ARR_BYTES);
            }
            uint32_t acol = ((lane >> 4) << 4) + s * 32;
#pragma unroll
            for (int mt = 0; mt < 4; mt++) {
                uint32_t ah[4], al[4];
                int rowA = wm * 64 + mt * 16 + (lane & 15);
                uint32_t ad = stage + rowA * 80 + acol;
                ldsm4(ah, ad);
                ldsm4(al, ad + ARR_BYTES);
#pragma unroll
                for (int nt = 0; nt < 4; nt++) {
                    const uint32_t* bhf = &bh[nt >> 1][(nt & 1) * 2];
                    const uint32_t* blf = &bl[nt >> 1][(nt & 1) * 2];
                    mma16816(c[mt][nt], ah, bhf);
                    mma16816(c[mt][nt], ah, blf);
                    mma16816(c[mt][nt], al, bhf);
                }
            }
        }
        __syncthreads();
    }

    // ---------------- epilogues ----------------
    const int g = lane >> 2, tg = lane & 3;
    if (MODE == 1) {
        // GRU over chunk cols [r(40)|z(40)|n(40)]: SMEM exchange in stage area
        const int ch = blockIdx.x;
        float* scr = reinterpret_cast<float*>(smem);  // 64 x 128 fp32 = 32KB
#pragma unroll
        for (int p = 0; p < 2; p++) {
            if (wm == p) {
#pragma unroll
                for (int mt = 0; mt < 4; mt++)
#pragma unroll
                    for (int half = 0; half < 2; half++) {
                        int lr = mt * 16 + g + half * 8;
#pragma unroll
                        for (int nt = 0; nt < 4; nt++) {
                            int colL = wn * 32 + nt * 8 + tg * 2;
                            scr[lr * 128 + colL] = c[mt][nt][2 * half + 0];
                            scr[lr * 128 + colL + 1] = c[mt][nt][2 * half + 1];
                        }
                    }
            }
            __syncthreads();
#pragma unroll
            for (int it = 0; it < 5; it++) {
                int item = tid + 256 * it;          // [0,1280) = 64 rows x 20 pairs
                int lr = item / 20, h2 = (item - lr * 20) * 2;
                int row = m0 + p * 64 + lr;
                __nv_bfloat16 hh[2], ll[2];
#pragma unroll
                for (int e = 0; e < 2; e++) {
                    int h = h2 + e;
                    int hp = ch * 40 + h;
                    float r = fsig(scr[lr * 128 + h] + biasS[h]);
                    float z = fsig(scr[lr * 128 + 40 + h] + biasS[40 + h]);
                    float nn = ftanh_(scr[lr * 128 + 80 + h] + biasS[80 + h]
                                      + r * g_gh[480 + hp]);
                    float hv = (1.0f - z) * nn + z * aux2[hp];
                    fsplit(hv, hh[e], ll[e]);
                }
                size_t o = (size_t)row * KPAD + ch * 40 + h2;
                *reinterpret_cast<uint32_t*>(g_A2h + o) = *reinterpret_cast<uint32_t*>(hh);
                *reinterpret_cast<uint32_t*>(g_A2l + o) = *reinterpret_cast<uint32_t*>(ll);
            }
            __syncthreads();
        }
    } else if (MODE == 2) {
#pragma unroll
        for (int mt = 0; mt < 4; mt++)
#pragma unroll
            for (int half = 0; half < 2; half++) {
                int row = m0 + wm * 64 + mt * 16 + g + half * 8;
#pragma unroll
                for (int nt = 0; nt < 4; nt++) {
                    int colL = wn * 32 + nt * 8 + tg * 2;
                    int col = n0 + colL;
                    float2 u = *reinterpret_cast<const float2*>(
                        aux2 + (size_t)row * OUT_HID + col);
                    float t0 = fmaxf(c[mt][nt][2 * half + 0] + biasS[colL], 0.f);
                    float t1 = fmaxf(c[mt][nt][2 * half + 1] + biasS[colL + 1], 0.f);
                    float v0 = (u.x > 0.65f) ? t0 * (1.0f / 0.35f) : 0.f;
                    float v1 = (u.y > 0.65f) ? t1 * (1.0f / 0.35f) : 0.f;
                    __nv_bfloat16 h0, l0, h1, l1;
                    fsplit(v0, h0, l0);
                    fsplit(v1, h1, l1);
                    __nv_bfloat162 hp; hp.x = h0; hp.y = h1;
                    __nv_bfloat162 lp; lp.x = l0; lp.y = l1;
                    *reinterpret_cast<__nv_bfloat162*>(g_O1h + (size_t)row * OUT_HID + col) = hp;
                    *reinterpret_cast<__nv_bfloat162*>(g_O1l + (size_t)row * OUT_HID + col) = lp;
                }
            }
    } else {  // MODE 3: n = s*8+o; warp covers s = wn*4+nt, o = tg*2,+1
#pragma unroll
        for (int mt = 0; mt < 4; mt++) {
#pragma unroll
            for (int half = 0; half < 2; half++) {
                int row = m0 + wm * 64 + mt * 16 + g + half * 8;
                int b = row & (B_DIM - 1);
                int j = row >> 12;
                float2 iv = *reinterpret_cast<const float2*>(g_inno + b * O_DIM + tg * 2);
#pragma unroll
                for (int nt = 0; nt < 4; nt++) {
                    int colL = wn * 32 + nt * 8 + tg * 2;
                    float v = (c[mt][nt][2 * half + 0] + biasS[colL]) * iv.x
                            + (c[mt][nt][2 * half + 1] + biasS[colL + 1]) * iv.y;
                    v += __shfl_xor_sync(0xffffffffu, v, 1);
                    v += __shfl_xor_sync(0xffffffffu, v, 2);
                    if (tg == 0) {
                        int s = wn * 4 + nt;
                        ens[(size_t)b * (J_DIM * S_DIM) + j * S_DIM + s] =
                            g_xpred[b * S_DIM + s] + v;
                    }
                }
            }
        }
    }
}

// ---------------- mean / unbiased var over J --------------------------------
__global__ void reduce_kernel(const float* __restrict__ ens, float* __restrict__ out) {
    int idx = blockIdx.x * blockDim.x + threadIdx.x;
    if (idx >= B_DIM * S_DIM) return;
    int b = idx >> 4, s = idx & 15;
    const float* p = ens + (size_t)b * (J_DIM * S_DIM) + s;
    float v[J_DIM], sum = 0.f;
#pragma unroll
    for (int j = 0; j < J_DIM; j++) { v[j] = p[j * S_DIM]; sum += v[j]; }
    float mean = sum * (1.0f / J_DIM);
    float var = 0.f;
#pragma unroll
    for (int j = 0; j < J_DIM; j++) { float d = v[j] - mean; var = fmaf(d, d, var); }
    out[idx] = mean;
    out[B_DIM * S_DIM + idx] = var * (1.0f / (J_DIM - 1));
}

// ---------------- launcher --------------------------------------------------
extern "C" void kernel_launch(void* const* d_in, const int* in_sizes, int n_in,
                              void* d_out, int out_size) {
    const float* y_t    = (const float*)d_in[0];
    const float* xprev  = (const float*)d_in[1];
    const float* F      = (const float*)d_in[2];
    const float* H      = (const float*)d_in[3];
    const float* W_fc   = (const float*)d_in[4];
    const float* b_fc   = (const float*)d_in[5];
    const float* W_ih   = (const float*)d_in[6];
    const float* W_hh   = (const float*)d_in[7];
    const float* b_ih   = (const float*)d_in[8];
    const float* b_hh   = (const float*)d_in[9];
    const float* W_out1 = (const float*)d_in[10];
    const float* b_out1 = (const float*)d_in[11];
    const float* W_out2 = (const float*)d_in[12];
    const float* b_out2 = (const float*)d_in[13];
    const float* h_init = (const float*)d_in[14];
    const float* u1     = (const float*)d_in[15];
    const float* u2     = (const float*)d_in[16];

    float* out = (float*)d_out;
    float* ens = out + 2 * B_DIM * S_DIM + 1;

    cudaFuncSetAttribute((const void*)gemm_mma<1>, cudaFuncAttributeMaxDynamicSharedMemorySize, GEMM_SMEM);
    cudaFuncSetAttribute((const void*)gemm_mma<2>, cudaFuncAttributeMaxDynamicSharedMemorySize, GEMM_SMEM);
    cudaFuncSetAttribute((const void*)gemm_mma<3>, cudaFuncAttributeMaxDynamicSharedMemorySize, GEMM_SMEM);

    gh_kernel<<<3, 256>>>(W_hh, b_hh, h_init, out);
    bprep_kernel<<<3, 256>>>(b_ih);
    prep_kernel<<<B_DIM, 256>>>(y_t, xprev, F, H, W_fc, b_fc);
    convW_kernel<<<(768 * KPAD + 512 * KPAD + 128 * 512 + 255) / 256, 256>>>(W_ih, W_out1, W_out2);
    conv1_kernel<<<(JB * 64) / 256, 256>>>(u1);

    // G1 + GRU fused epilogue -> g_A2
    gemm_mma<1><<<dim3(6, JB / 128), 256, GEMM_SMEM>>>(nullptr, h_init, nullptr);

    // G2: O1 = split(relu(A2 @ Wo1^T + b) * mask2)
    gemm_mma<2><<<dim3(4, JB / 128), 256, GEMM_SMEM>>>(b_out1, u2, nullptr);

    // G3: ensemble = xpred + (O1 @ Wo2^T + b2) . inno
    gemm_mma<3><<<dim3(1, JB / 128), 256, GEMM_SMEM>>>(b_out2, nullptr, ens);

    reduce_kernel<<<(B_DIM * S_DIM) / 256, 256>>>(ens, out);
}